// round 15
// baseline (speedup 1.0000x reference)
#include <cuda_runtime.h>
#include <cuda_fp16.h>
#include <math.h>
#include <stdint.h>

#define TWO_PI 6.28318530717958647692f

// Scratch
// g_Bq[h][o(128)][slot(32), stride 36]: uint4 = half2{P0,P1,-Q1,P2}
//   slot = kt*8 + tg + 4*cpr -> channels (kt*16 + 4tg + 2cpr, +1)
// g_Bs: same indexing, half2{-Q2}
__device__ uint4 g_Bq[128 * 4608];
__device__ uint32_t g_Bs[128 * 4608];
__device__ uint32_t g_raw[16777216];  // fp16 raw conv out: [part][n][h][w][o]/2
__device__ float g_stats[512];        // [(part*128+o)*2 + {sum,sq}]
__device__ unsigned int g_bar;

__device__ __forceinline__ uint32_t pack_h2(float lo, float hi) {
    uint32_t r;
    asm("cvt.rn.f16x2.f32 %0, %1, %2;" : "=r"(r) : "f"(hi), "f"(lo));
    return r;
}
__device__ __forceinline__ void mma_f16(float* d, const uint32_t* a,
                                        const uint32_t* b) {
    asm volatile(
        "mma.sync.aligned.m16n8k16.row.col.f32.f16.f16.f32 "
        "{%0,%1,%2,%3}, {%4,%5,%6,%7}, {%8,%9}, {%0,%1,%2,%3};"
        : "+f"(d[0]), "+f"(d[1]), "+f"(d[2]), "+f"(d[3])
        : "r"(a[0]), "r"(a[1]), "r"(a[2]), "r"(a[3]), "r"(b[0]), "r"(b[1]));
}
__device__ __forceinline__ uint32_t h2u(__half2 v) { return *(uint32_t*)&v; }
__device__ __forceinline__ __half2 u2h(uint32_t u) { return *(__half2*)&u; }

// ---------------------------------------------------------------------------
__global__ void zero_stats_kernel() {
    if (threadIdx.x < 512) g_stats[threadIdx.x] = 0.f;
    if (threadIdx.x == 0) g_bar = 0u;
}

__global__ void precompute_B_kernel(const float* __restrict__ filters) {
    __shared__ float ct[128], st[128];
    int h = blockIdx.x, t = threadIdx.x;
    if (t < 128) {
        float s_, c_;
        sincosf(TWO_PI * (float)t * (1.f / 128.f), &s_, &c_);
        ct[t] = c_; st[t] = s_;
    }
    __syncthreads();
    for (int e = t; e < 4096; e += blockDim.x) {
        int o = e >> 5, slot = e & 31;
        int kt = slot >> 3, r = slot & 7;
        int cpr = r >> 2, tg = r & 3;
        int c = kt * 16 + 4 * tg + 2 * cpr;
        uint32_t pk[5];
        #pragma unroll
        for (int j = 0; j < 5; j++) {
            int v = (j + 1) >> 1;                   // {0,1,1,2,2}
            bool sn = (j > 0) && ((j & 1) == 0);    // -Q1 / -Q2
            float b0 = 0.f, b1 = 0.f;
            #pragma unroll
            for (int u = 0; u < 3; u++) {
                int a = (h * u) & 127;
                float tr = sn ? st[a] : ct[a];
                b0 = fmaf(tr, filters[(u * 3 + v) * 8192 + c * 128 + o], b0);
                b1 = fmaf(tr, filters[(u * 3 + v) * 8192 + (c + 1) * 128 + o], b1);
            }
            if (sn) { b0 = -b0; b1 = -b1; }
            pk[j] = pack_h2(b0, b1);
        }
        g_Bq[h * 4608 + o * 36 + slot] = make_uint4(pk[0], pk[1], pk[2], pk[3]);
        g_Bs[h * 4608 + o * 36 + slot] = pk[4];
    }
}

// ---------------------------------------------------------------------------
// Conv + fused BN: 128 CTAs (one per h, all co-resident), 256 threads.
// K-permuted m16n8k16 fp16 GEMM: thread tg owns channels 4tg..4tg+3 ->
// A-fragments load as two LDG.128 (r,i) per (pixel,kt); rows gid/gid+8 =
// (n=gid, part0/part1) so one load pair feeds both S and D fragments.
// Phase 1 writes fp16 raw to g_raw + reg-resident per-part BN stats.
// Phase 2: grid barrier, BN params, apply to own h-slice, write fp32 out.
#define BQ_BYTES 73728
#define BS_BYTES 18432
#define RED_BYTE (BQ_BYTES + BS_BYTES)
#define SMEM_CONV (RED_BYTE + 2048)

__global__ __launch_bounds__(256, 1) void conv_mma_kernel(
    const float* __restrict__ xr, const float* __restrict__ xi,
    float* __restrict__ out,
    const float* __restrict__ gr, const float* __restrict__ br,
    const float* __restrict__ gi, const float* __restrict__ bi)
{
    extern __shared__ char smem[];
    const uint4* BQ = (const uint4*)smem;
    const __half2* BS = (const __half2*)(smem + BQ_BYTES);
    float* red = (float*)(smem + RED_BYTE);

    const int h = blockIdx.x, t = threadIdx.x;
    const int lane = t & 31, wid = t >> 5;
    const int gid = lane >> 2, tg = lane & 3;

    // load resident B
    {
        const uint4* sq = g_Bq + h * 4608;
        uint4* dq = (uint4*)smem;
        for (int g = t; g < 4608; g += 256) dq[g] = sq[g];
        const uint4* ss = (const uint4*)(g_Bs + h * 4608);
        uint4* ds = (uint4*)(smem + BQ_BYTES);
        for (int g = t; g < 1152; g += 256) ds[g] = ss[g];
    }
    for (int i = t; i < 512; i += 256) red[i] = 0.f;
    __syncthreads();

    // BN stats: per nt, per part, cols (2tg, 2tg+1): 8 arrays x 16
    float s0l[16], s0h[16], q0l[16], q0h[16];
    float s1l[16], s1h[16], q1l[16], q1h[16];
    #pragma unroll
    for (int i = 0; i < 16; i++) {
        s0l[i] = 0.f; s0h[i] = 0.f; q0l[i] = 0.f; q0h[i] = 0.f;
        s1l[i] = 0.f; s1h[i] = 0.f; q1l[i] = 0.f; q1h[i] = 0.f;
    }

    // this thread's single X row: n = gid
    const float* xrow_r = xr + ((size_t)(gid * 128 + h) * 128) * 64 + 4 * tg;
    const float* xrow_i = xi + ((size_t)(gid * 128 + h) * 128) * 64 + 4 * tg;

    #pragma unroll 1
    for (int it = 0; it < 8; it++) {
        const int w = it * 8 + wid;          // 0..63
        // ---- a-fragments for pixels w and w+64 ----
        uint32_t aw[16], av[16];
        #pragma unroll
        for (int px = 0; px < 2; px++) {
            const int ww = w + px * 64;
            const float4* pr = (const float4*)(xrow_r + ww * 64);
            const float4* pi = (const float4*)(xrow_i + ww * 64);
            uint32_t* dst = px ? av : aw;
            #pragma unroll
            for (int kt = 0; kt < 4; kt++) {
                float4 r = pr[kt * 4];
                float4 ii = pi[kt * 4];
                dst[kt * 4 + 0] = pack_h2(r.x + ii.x, r.y + ii.y);   // S lo
                dst[kt * 4 + 1] = pack_h2(ii.x - r.x, ii.y - r.y);   // D lo
                dst[kt * 4 + 2] = pack_h2(r.z + ii.z, r.w + ii.w);   // S hi
                dst[kt * 4 + 3] = pack_h2(ii.z - r.z, ii.w - r.w);   // D hi
            }
        }

        float s1, c1f, s2, c2f;
        float ang = TWO_PI * (float)w * (1.f / 128.f);
        sincosf(ang, &s1, &c1f);
        sincosf(2.f * ang, &s2, &c2f);
        const __half2 hc1 = __float2half2_rn(c1f);
        const __half2 hs1 = __float2half2_rn(s1);
        const __half2 hc2 = __float2half2_rn(c2f);
        const __half2 hs2 = __float2half2_rn(s2);

        // raw out base: [part=0][n=gid][h][w], half2 index
        const uint32_t rb = ((gid * 128 + h) * 128 + w) * 64 + tg;

        #pragma unroll
        for (int nt = 0; nt < 16; nt++) {
            float accw[4] = {0.f, 0.f, 0.f, 0.f};
            float accv[4] = {0.f, 0.f, 0.f, 0.f};
            const int ob = (nt * 8 + gid) * 36;
            #pragma unroll
            for (int kt = 0; kt < 4; kt++) {
                const int cp0 = ob + kt * 8 + tg;
                uint4 v0 = BQ[cp0];
                uint4 v1 = BQ[cp0 + 4];
                __half2 z0 = BS[cp0];
                __half2 z1 = BS[cp0 + 4];
                __half2 e0 = __hfma2(hc2, u2h(v0.w), u2h(v0.x));
                e0 = __hfma2(hs2, z0, e0);
                __half2 o0 = __hmul2(hc1, u2h(v0.y));
                o0 = __hfma2(hs1, u2h(v0.z), o0);
                __half2 e1 = __hfma2(hc2, u2h(v1.w), u2h(v1.x));
                e1 = __hfma2(hs2, z1, e1);
                __half2 o1 = __hmul2(hc1, u2h(v1.y));
                o1 = __hfma2(hs1, u2h(v1.z), o1);
                uint32_t bw[2] = {h2u(__hadd2(e0, o0)), h2u(__hadd2(e1, o1))};
                uint32_t bv[2] = {h2u(__hsub2(e0, o0)), h2u(__hsub2(e1, o1))};
                mma_f16(accw, &aw[kt * 4], bw);
                mma_f16(accv, &av[kt * 4], bv);
            }
            // store fp16 raw: c0,c1 = part0; c2,c3 = part1; pixels w and w+64
            const uint32_t ro = rb + nt * 4;
            g_raw[ro] = pack_h2(accw[0], accw[1]);
            g_raw[ro + 8388608] = pack_h2(accw[2], accw[3]);
            g_raw[ro + 4096] = pack_h2(accv[0], accv[1]);
            g_raw[ro + 8392704] = pack_h2(accv[2], accv[3]);
            // stats (fp32, pre-rounding)
            s0l[nt] += accw[0] + accv[0];
            s0h[nt] += accw[1] + accv[1];
            q0l[nt] = fmaf(accw[0], accw[0], q0l[nt]);
            q0l[nt] = fmaf(accv[0], accv[0], q0l[nt]);
            q0h[nt] = fmaf(accw[1], accw[1], q0h[nt]);
            q0h[nt] = fmaf(accv[1], accv[1], q0h[nt]);
            s1l[nt] += accw[2] + accv[2];
            s1h[nt] += accw[3] + accv[3];
            q1l[nt] = fmaf(accw[2], accw[2], q1l[nt]);
            q1l[nt] = fmaf(accv[2], accv[2], q1l[nt]);
            q1h[nt] = fmaf(accw[3], accw[3], q1h[nt]);
            q1h[nt] = fmaf(accv[3], accv[3], q1h[nt]);
        }
    }

    // ---- BN stats: reduce over gid lanes (xor 4,8,16), smem, global ----
    #pragma unroll
    for (int nt = 0; nt < 16; nt++) {
        #pragma unroll
        for (int m = 4; m <= 16; m <<= 1) {
            s0l[nt] += __shfl_xor_sync(~0u, s0l[nt], m);
            s0h[nt] += __shfl_xor_sync(~0u, s0h[nt], m);
            q0l[nt] += __shfl_xor_sync(~0u, q0l[nt], m);
            q0h[nt] += __shfl_xor_sync(~0u, q0h[nt], m);
            s1l[nt] += __shfl_xor_sync(~0u, s1l[nt], m);
            s1h[nt] += __shfl_xor_sync(~0u, s1h[nt], m);
            q1l[nt] += __shfl_xor_sync(~0u, q1l[nt], m);
            q1h[nt] += __shfl_xor_sync(~0u, q1h[nt], m);
        }
    }
    if (lane < 4) {   // tg = lane
        #pragma unroll
        for (int nt = 0; nt < 16; nt++) {
            int o = nt * 8 + 2 * tg;
            atomicAdd(&red[o * 2 + 0], s0l[nt]);
            atomicAdd(&red[o * 2 + 1], q0l[nt]);
            atomicAdd(&red[(o + 1) * 2 + 0], s0h[nt]);
            atomicAdd(&red[(o + 1) * 2 + 1], q0h[nt]);
            atomicAdd(&red[(128 + o) * 2 + 0], s1l[nt]);
            atomicAdd(&red[(128 + o) * 2 + 1], q1l[nt]);
            atomicAdd(&red[(128 + o + 1) * 2 + 0], s1h[nt]);
            atomicAdd(&red[(128 + o + 1) * 2 + 1], q1h[nt]);
        }
    }
    __syncthreads();
    for (int i = t; i < 512; i += 256) atomicAdd(&g_stats[i], red[i]);
    __threadfence();
    __syncthreads();

    // ---- grid-wide barrier (all 128 CTAs co-resident) ----
    if (t == 0) {
        atomicAdd(&g_bar, 1u);
        while (atomicAdd(&g_bar, 0u) < 128u) __nanosleep(128);
    }
    __syncthreads();
    __threadfence();

    // ---- BN params (redundant per CTA) ----
    {
        int p2 = t >> 7, o = t & 127;
        float sum = g_stats[2 * t], sq = g_stats[2 * t + 1];
        const float inv = 1.f / 131072.f;
        float mean = sum * inv;
        float var = fmaf(-mean, mean, sq * inv);
        float gamma = p2 ? gi[o] : gr[o];
        float beta = p2 ? bi[o] : br[o];
        float a = gamma * rsqrtf(var + 1e-3f);
        red[2 * t] = a;
        red[2 * t + 1] = fmaf(-mean, a, beta);
    }
    __syncthreads();

    // ---- apply BN + LeakyReLU to this CTA's h-slice ----
    {
        const int o8 = (t & 15) * 8;   // fixed o-octet per thread
        const int wb = t >> 4;         // w base (0..15)
        #pragma unroll
        for (int p = 0; p < 2; p++) {
            float pa[8], pb[8];
            #pragma unroll
            for (int q = 0; q < 8; q++) {
                pa[q] = red[p * 256 + (o8 + q) * 2];
                pb[q] = red[p * 256 + (o8 + q) * 2 + 1];
            }
            #pragma unroll 1
            for (int n = 0; n < 8; n++) {
                const uint4* src = (const uint4*)(g_raw + (size_t)p * 8388608 +
                                                  ((size_t)(n * 128 + h) * 128) * 64);
                float* dst = out + (size_t)p * 16777216 +
                             (((size_t)n * 128 + h) * 128) * 128;
                #pragma unroll 2
                for (int k = 0; k < 8; k++) {
                    int w = wb + k * 16;
                    uint4 v = src[w * 16 + (t & 15)];
                    float2 f0 = __half22float2(u2h(v.x));
                    float2 f1 = __half22float2(u2h(v.y));
                    float2 f2 = __half22float2(u2h(v.z));
                    float2 f3 = __half22float2(u2h(v.w));
                    float4 lo, hi, vv;
                    float x;
                    x = fmaf(pa[0], f0.x, pb[0]); lo.x = x >= 0.f ? x : 0.2f * x;
                    x = fmaf(pa[1], f0.y, pb[1]); lo.y = x >= 0.f ? x : 0.2f * x;
                    x = fmaf(pa[2], f1.x, pb[2]); lo.z = x >= 0.f ? x : 0.2f * x;
                    x = fmaf(pa[3], f1.y, pb[3]); lo.w = x >= 0.f ? x : 0.2f * x;
                    x = fmaf(pa[4], f2.x, pb[4]); hi.x = x >= 0.f ? x : 0.2f * x;
                    x = fmaf(pa[5], f2.y, pb[5]); hi.y = x >= 0.f ? x : 0.2f * x;
                    x = fmaf(pa[6], f3.x, pb[6]); hi.z = x >= 0.f ? x : 0.2f * x;
                    x = fmaf(pa[7], f3.y, pb[7]); hi.w = x >= 0.f ? x : 0.2f * x;
                    *(float4*)(dst + (size_t)w * 128 + o8) = lo;
                    *(float4*)(dst + (size_t)w * 128 + o8 + 4) = hi;
                    (void)vv;
                }
            }
        }
    }
}

// ---------------------------------------------------------------------------
extern "C" void kernel_launch(void* const* d_in, const int* in_sizes, int n_in,
                              void* d_out, int out_size) {
    const float* xr = (const float*)d_in[0];
    const float* xi = (const float*)d_in[1];
    const float* f  = (const float*)d_in[2];
    const float* gr = (const float*)d_in[3];
    const float* br = (const float*)d_in[4];
    const float* gi = (const float*)d_in[5];
    const float* bi = (const float*)d_in[6];
    float* out = (float*)d_out;

    cudaFuncSetAttribute(conv_mma_kernel,
                         cudaFuncAttributeMaxDynamicSharedMemorySize, SMEM_CONV);

    zero_stats_kernel<<<1, 512>>>();
    precompute_B_kernel<<<128, 256>>>(f);
    conv_mma_kernel<<<128, 256, SMEM_CONV>>>(xr, xi, out, gr, br, gi, bi);
}

// round 16
// speedup vs baseline: 1.1893x; 1.1893x over previous
#include <cuda_runtime.h>
#include <cuda_fp16.h>
#include <math.h>
#include <stdint.h>

#define TWO_PI 6.28318530717958647692f

// Scratch
// g_Bq[h][o(128)][cp(32), stride 36]: uint4 = half2{P0,P1,-Q1,P2} for c=2cp,2cp+1
// g_Bs[h][o][cp, stride 36]        : uint32 = half2{-Q2}
__device__ uint4 g_Bq[128 * 4608];
__device__ uint32_t g_Bs[128 * 4608];
__device__ float g_stats[512];        // [(part*128+o)*2 + {sum,sq}]
__device__ unsigned int g_bar;

__device__ __forceinline__ uint32_t pack_h2(float lo, float hi) {
    uint32_t r;
    asm("cvt.rn.f16x2.f32 %0, %1, %2;" : "=r"(r) : "f"(hi), "f"(lo));
    return r;
}
__device__ __forceinline__ void mma_f16(float* d, const uint32_t* a,
                                        const uint32_t* b) {
    asm volatile(
        "mma.sync.aligned.m16n8k16.row.col.f32.f16.f16.f32 "
        "{%0,%1,%2,%3}, {%4,%5,%6,%7}, {%8,%9}, {%0,%1,%2,%3};"
        : "+f"(d[0]), "+f"(d[1]), "+f"(d[2]), "+f"(d[3])
        : "r"(a[0]), "r"(a[1]), "r"(a[2]), "r"(a[3]), "r"(b[0]), "r"(b[1]));
}
__device__ __forceinline__ uint32_t h2u(__half2 v) { return *(uint32_t*)&v; }
__device__ __forceinline__ __half2 u2h(uint32_t u) { return *(__half2*)&u; }

// ---------------------------------------------------------------------------
__global__ void zero_stats_kernel() {
    if (threadIdx.x < 512) g_stats[threadIdx.x] = 0.f;
    if (threadIdx.x == 0) g_bar = 0u;
}

__global__ void precompute_B_kernel(const float* __restrict__ filters) {
    __shared__ float ct[128], st[128];
    int h = blockIdx.x, t = threadIdx.x;
    if (t < 128) {
        float s_, c_;
        sincosf(TWO_PI * (float)t * (1.f / 128.f), &s_, &c_);
        ct[t] = c_; st[t] = s_;
    }
    __syncthreads();
    for (int e = t; e < 4096; e += blockDim.x) {
        int o = e >> 5, cp = e & 31, c = 2 * cp;
        uint32_t pk[5];
        #pragma unroll
        for (int j = 0; j < 5; j++) {
            int v = (j + 1) >> 1;                   // {0,1,1,2,2}
            bool sn = (j > 0) && ((j & 1) == 0);    // -Q1 / -Q2
            float b0 = 0.f, b1 = 0.f;
            #pragma unroll
            for (int u = 0; u < 3; u++) {
                int a = (h * u) & 127;
                float tr = sn ? st[a] : ct[a];
                b0 = fmaf(tr, filters[(u * 3 + v) * 8192 + c * 128 + o], b0);
                b1 = fmaf(tr, filters[(u * 3 + v) * 8192 + (c + 1) * 128 + o], b1);
            }
            if (sn) { b0 = -b0; b1 = -b1; }
            pk[j] = pack_h2(b0, b1);
        }
        g_Bq[h * 4608 + o * 36 + cp] = make_uint4(pk[0], pk[1], pk[2], pk[3]);
        g_Bs[h * 4608 + o * 36 + cp] = pk[4];
    }
}

// ---------------------------------------------------------------------------
// Conv + fused BN: 128 CTAs (one per h, all co-resident), 512 threads
// (16 warps = 4/SMSP for latency hiding). Warps split the o-dimension:
// ohalf = wid>>3 -> nt in [ohalf*8, ohalf*8+8). Each warp: w-pair (w, w+64)
// per iteration x 8 iterations (w = it*8 + (wid&7)).
// b-fragments built in half2 from smem B (uint4 + lds.32, conflict-free
// stride 36); m16n8k16 fp16 GEMM K=64. Phase 2: grid barrier, BN apply.
#define BQ_BYTES 73728
#define BS_BYTES 18432
#define RED_BYTE (BQ_BYTES + BS_BYTES)
#define SMEM_CONV (RED_BYTE + 2048)

__global__ __launch_bounds__(512, 1) void conv_mma_kernel(
    const float* __restrict__ xr, const float* __restrict__ xi,
    float* __restrict__ out,
    const float* __restrict__ gr, const float* __restrict__ br,
    const float* __restrict__ gi, const float* __restrict__ bi)
{
    extern __shared__ char smem[];
    const uint4* BQ = (const uint4*)smem;
    const __half2* BS = (const __half2*)(smem + BQ_BYTES);
    float* red = (float*)(smem + RED_BYTE);

    const int h = blockIdx.x, t = threadIdx.x;
    const int lane = t & 31, wid = t >> 5;
    const int gid = lane >> 2, tg = lane & 3;
    const int n0 = gid >> 1, part = gid & 1;
    const int ohalf = wid >> 3;          // 0/1: which 64 o's this warp owns
    const int wlid = wid & 7;            // w lane within iteration

    // load resident B
    {
        const uint4* sq = g_Bq + h * 4608;
        uint4* dq = (uint4*)smem;
        for (int g = t; g < 4608; g += 512) dq[g] = sq[g];
        const uint4* ss = (const uint4*)(g_Bs + h * 4608);
        uint4* ds = (uint4*)(smem + BQ_BYTES);
        for (int g = t; g < 1152; g += 512) ds[g] = ss[g];
    }
    if (t < 512) red[t] = 0.f;
    __syncthreads();

    // persistent BN stat registers: per nt8, o-pair (2tg, 2tg+1)
    float ss0[8], qq0[8], ss1[8], qq1[8];
    #pragma unroll
    for (int i = 0; i < 8; i++) { ss0[i] = 0.f; qq0[i] = 0.f; ss1[i] = 0.f; qq1[i] = 0.f; }

    const float* xr0 = xr + ((size_t)(n0 * 128 + h) * 128) * 64;
    const float* xi0 = xi + ((size_t)(n0 * 128 + h) * 128) * 64;
    const float* xr4 = xr + ((size_t)((n0 + 4) * 128 + h) * 128) * 64;
    const float* xi4 = xi + ((size_t)((n0 + 4) * 128 + h) * 128) * 64;

    #pragma unroll 1
    for (int it = 0; it < 8; it++) {
        const int w = it * 8 + wlid;         // 0..63
        // ---- a-fragments for pixels w and w+64 (unscaled S/D rows) ----
        uint32_t aw[16], av[16];
        #pragma unroll
        for (int px = 0; px < 2; px++) {
            const int ww = w + px * 64;
            const float* pr0 = xr0 + ww * 64;
            const float* pi0 = xi0 + ww * 64;
            const float* pr4 = xr4 + ww * 64;
            const float* pi4 = xi4 + ww * 64;
            uint32_t* dst = px ? av : aw;
            #pragma unroll
            for (int kt = 0; kt < 4; kt++) {
                int c0 = kt * 16 + 2 * tg;
                float2 r0a = *(const float2*)(pr0 + c0);
                float2 i0a = *(const float2*)(pi0 + c0);
                float2 r0b = *(const float2*)(pr0 + c0 + 8);
                float2 i0b = *(const float2*)(pi0 + c0 + 8);
                float2 r4a = *(const float2*)(pr4 + c0);
                float2 i4a = *(const float2*)(pi4 + c0);
                float2 r4b = *(const float2*)(pr4 + c0 + 8);
                float2 i4b = *(const float2*)(pi4 + c0 + 8);
                float v0x = part ? (i0a.x - r0a.x) : (r0a.x + i0a.x);
                float v0y = part ? (i0a.y - r0a.y) : (r0a.y + i0a.y);
                float v4x = part ? (i4a.x - r4a.x) : (r4a.x + i4a.x);
                float v4y = part ? (i4a.y - r4a.y) : (r4a.y + i4a.y);
                float b0x = part ? (i0b.x - r0b.x) : (r0b.x + i0b.x);
                float b0y = part ? (i0b.y - r0b.y) : (r0b.y + i0b.y);
                float b4x = part ? (i4b.x - r4b.x) : (r4b.x + i4b.x);
                float b4y = part ? (i4b.y - r4b.y) : (r4b.y + i4b.y);
                dst[kt * 4 + 0] = pack_h2(v0x, v0y);
                dst[kt * 4 + 1] = pack_h2(v4x, v4y);
                dst[kt * 4 + 2] = pack_h2(b0x, b0y);
                dst[kt * 4 + 3] = pack_h2(b4x, b4y);
            }
        }

        float s1, c1f, s2, c2f;
        float ang = TWO_PI * (float)w * (1.f / 128.f);
        sincosf(ang, &s1, &c1f);
        sincosf(2.f * ang, &s2, &c2f);
        const __half2 hc1 = __float2half2_rn(c1f);
        const __half2 hs1 = __float2half2_rn(s1);
        const __half2 hc2 = __float2half2_rn(c2f);
        const __half2 hs2 = __float2half2_rn(s2);

        const size_t base_w = (size_t)part * 16777216 +
                              (((size_t)(n0 * 128 + h)) * 128 + w) * 128;

        #pragma unroll
        for (int nt8 = 0; nt8 < 8; nt8++) {
            const int nt = ohalf * 8 + nt8;
            float accw[4] = {0.f, 0.f, 0.f, 0.f};
            float accv[4] = {0.f, 0.f, 0.f, 0.f};
            const int ob = (nt * 8 + gid) * 36;
            #pragma unroll
            for (int kt = 0; kt < 4; kt++) {
                const int cp0 = ob + kt * 8 + tg;
                uint4 v0 = BQ[cp0];
                uint4 v1 = BQ[cp0 + 4];
                __half2 z0 = BS[cp0];
                __half2 z1 = BS[cp0 + 4];
                __half2 e0 = __hfma2(hc2, u2h(v0.w), u2h(v0.x));
                e0 = __hfma2(hs2, z0, e0);
                __half2 o0 = __hmul2(hc1, u2h(v0.y));
                o0 = __hfma2(hs1, u2h(v0.z), o0);
                __half2 e1 = __hfma2(hc2, u2h(v1.w), u2h(v1.x));
                e1 = __hfma2(hs2, z1, e1);
                __half2 o1 = __hmul2(hc1, u2h(v1.y));
                o1 = __hfma2(hs1, u2h(v1.z), o1);
                uint32_t bw[2] = {h2u(__hadd2(e0, o0)), h2u(__hadd2(e1, o1))};
                uint32_t bv[2] = {h2u(__hsub2(e0, o0)), h2u(__hsub2(e1, o1))};
                mma_f16(accw, &aw[kt * 4], bw);
                mma_f16(accv, &av[kt * 4], bv);
            }
            const int o = nt * 8 + 2 * tg;
            *(float2*)(out + base_w + o) = make_float2(accw[0], accw[1]);
            *(float2*)(out + base_w + 8388608 + o) = make_float2(accw[2], accw[3]);
            *(float2*)(out + base_w + 8192 + o) = make_float2(accv[0], accv[1]);
            *(float2*)(out + base_w + 8388608 + 8192 + o) =
                make_float2(accv[2], accv[3]);
            ss0[nt8] += (accw[0] + accw[2]) + (accv[0] + accv[2]);
            qq0[nt8] = fmaf(accw[0], accw[0], qq0[nt8]);
            qq0[nt8] = fmaf(accw[2], accw[2], qq0[nt8]);
            qq0[nt8] = fmaf(accv[0], accv[0], qq0[nt8]);
            qq0[nt8] = fmaf(accv[2], accv[2], qq0[nt8]);
            ss1[nt8] += (accw[1] + accw[3]) + (accv[1] + accv[3]);
            qq1[nt8] = fmaf(accw[1], accw[1], qq1[nt8]);
            qq1[nt8] = fmaf(accw[3], accw[3], qq1[nt8]);
            qq1[nt8] = fmaf(accv[1], accv[1], qq1[nt8]);
            qq1[nt8] = fmaf(accv[3], accv[3], qq1[nt8]);
        }
    }

    // ---- BN stats: shuffle-reduce over n (xor 8,16), smem, global ----
    #pragma unroll
    for (int nt8 = 0; nt8 < 8; nt8++) {
        ss0[nt8] += __shfl_xor_sync(~0u, ss0[nt8], 8);
        ss0[nt8] += __shfl_xor_sync(~0u, ss0[nt8], 16);
        qq0[nt8] += __shfl_xor_sync(~0u, qq0[nt8], 8);
        qq0[nt8] += __shfl_xor_sync(~0u, qq0[nt8], 16);
        ss1[nt8] += __shfl_xor_sync(~0u, ss1[nt8], 8);
        ss1[nt8] += __shfl_xor_sync(~0u, ss1[nt8], 16);
        qq1[nt8] += __shfl_xor_sync(~0u, qq1[nt8], 8);
        qq1[nt8] += __shfl_xor_sync(~0u, qq1[nt8], 16);
    }
    if (lane < 8) {   // gid in {0,1}: part = gid, tg = lane&3
        #pragma unroll
        for (int nt8 = 0; nt8 < 8; nt8++) {
            int o = (ohalf * 8 + nt8) * 8 + 2 * tg;
            atomicAdd(&red[(part * 128 + o) * 2 + 0], ss0[nt8]);
            atomicAdd(&red[(part * 128 + o) * 2 + 1], qq0[nt8]);
            atomicAdd(&red[(part * 128 + o + 1) * 2 + 0], ss1[nt8]);
            atomicAdd(&red[(part * 128 + o + 1) * 2 + 1], qq1[nt8]);
        }
    }
    __syncthreads();
    if (t < 512) atomicAdd(&g_stats[t], red[t]);
    __threadfence();
    __syncthreads();

    // ---- grid-wide barrier (all 128 CTAs co-resident) ----
    if (t == 0) {
        atomicAdd(&g_bar, 1u);
        while (atomicAdd(&g_bar, 0u) < 128u) __nanosleep(128);
    }
    __syncthreads();
    __threadfence();

    // ---- BN params (redundant per CTA) ----
    if (t < 256) {
        int p2 = t >> 7, o = t & 127;
        float sum = g_stats[2 * t], sq = g_stats[2 * t + 1];
        const float inv = 1.f / 131072.f;
        float mean = sum * inv;
        float var = fmaf(-mean, mean, sq * inv);
        float gamma = p2 ? gi[o] : gr[o];
        float beta = p2 ? bi[o] : br[o];
        float a = gamma * rsqrtf(var + 1e-3f);
        red[2 * t] = a;
        red[2 * t + 1] = fmaf(-mean, a, beta);
    }
    __syncthreads();

    // ---- apply BN + LeakyReLU to this CTA's slice (in place) ----
    {
        const int ol = (t & 31) * 4;   // fixed o-range per thread
        #pragma unroll
        for (int p = 0; p < 2; p++) {
            const float a0 = red[p * 256 + (ol + 0) * 2];
            const float b0 = red[p * 256 + (ol + 0) * 2 + 1];
            const float a1 = red[p * 256 + (ol + 1) * 2];
            const float b1 = red[p * 256 + (ol + 1) * 2 + 1];
            const float a2 = red[p * 256 + (ol + 2) * 2];
            const float b2 = red[p * 256 + (ol + 2) * 2 + 1];
            const float a3 = red[p * 256 + (ol + 3) * 2];
            const float b3 = red[p * 256 + (ol + 3) * 2 + 1];
            #pragma unroll 1
            for (int n = 0; n < 8; n++) {
                float4* base = (float4*)(out + (size_t)p * 16777216 +
                                         (((size_t)n * 128 + h) << 14));
                #pragma unroll 4
                for (int i = t; i < 4096; i += 512) {
                    float4 x = base[i];
                    float v;
                    v = fmaf(a0, x.x, b0); x.x = v >= 0.f ? v : 0.2f * v;
                    v = fmaf(a1, x.y, b1); x.y = v >= 0.f ? v : 0.2f * v;
                    v = fmaf(a2, x.z, b2); x.z = v >= 0.f ? v : 0.2f * v;
                    v = fmaf(a3, x.w, b3); x.w = v >= 0.f ? v : 0.2f * v;
                    base[i] = x;
                }
            }
        }
    }
}

// ---------------------------------------------------------------------------
extern "C" void kernel_launch(void* const* d_in, const int* in_sizes, int n_in,
                              void* d_out, int out_size) {
    const float* xr = (const float*)d_in[0];
    const float* xi = (const float*)d_in[1];
    const float* f  = (const float*)d_in[2];
    const float* gr = (const float*)d_in[3];
    const float* br = (const float*)d_in[4];
    const float* gi = (const float*)d_in[5];
    const float* bi = (const float*)d_in[6];
    float* out = (float*)d_out;

    cudaFuncSetAttribute(conv_mma_kernel,
                         cudaFuncAttributeMaxDynamicSharedMemorySize, SMEM_CONV);

    zero_stats_kernel<<<1, 512>>>();
    precompute_B_kernel<<<128, 256>>>(f);
    conv_mma_kernel<<<128, 512, SMEM_CONV>>>(xr, xi, out, gr, br, gi, bi);
}